// round 1
// baseline (speedup 1.0000x reference)
#include <cuda_runtime.h>
#include <cstdint>

// Problem constants
#define NPROB 2048      // B*S = 8*256
#define DD    128       // feature dim (m = n = 128)
#define NITER 20

// K = (SCALE/eps) * log2(e) = 3000 * log2(e)
#define KCOEF 4328.085098989891f
#define TWOK  8656.170197979782f
// ot scale: n * SCALE / NPROB = 128*300/2048
#define OTSCALE 18.75f

// Scratch: per-problem transport plans (128 MiB), partial sums, ot matrix
__device__ float g_scratch[(size_t)NPROB * DD * DD];
__device__ float g_partial[16 * DD * DD];
__device__ float g_ot[DD * DD];

__device__ __forceinline__ float ex2f(float x) {
    float r; asm("ex2.approx.ftz.f32 %0, %1;" : "=f"(r) : "f"(x)); return r;
}
__device__ __forceinline__ float lg2f(float x) {
    float r; asm("lg2.approx.f32 %0, %1;" : "=f"(r) : "f"(x)); return r;
}

// One logsumexp sweep over 128 entries stored as float2{coord, pot} in shared.
// v_j = fmaf(twoK, coord_j, pot_j); returns -(7 + max_j v + log2(sum_j 2^(v - max)))
__device__ __forceinline__ float sweep_update(const float2* __restrict__ arr, float twoK) {
    const float4* a4 = reinterpret_cast<const float4*>(arr);
    float m0 = -1e30f, m1 = -1e30f, m2 = -1e30f, m3 = -1e30f;
#pragma unroll 8
    for (int q = 0; q < DD / 4; ++q) {
        float4 u = a4[2 * q];
        float4 w = a4[2 * q + 1];
        m0 = fmaxf(m0, fmaf(twoK, u.x, u.y));
        m1 = fmaxf(m1, fmaf(twoK, u.z, u.w));
        m2 = fmaxf(m2, fmaf(twoK, w.x, w.y));
        m3 = fmaxf(m3, fmaf(twoK, w.z, w.w));
    }
    float mx = fmaxf(fmaxf(m0, m1), fmaxf(m2, m3));
    float s0 = 0.f, s1 = 0.f, s2 = 0.f, s3 = 0.f;
#pragma unroll 8
    for (int q = 0; q < DD / 4; ++q) {
        float4 u = a4[2 * q];
        float4 w = a4[2 * q + 1];
        s0 += ex2f(fmaf(twoK, u.x, u.y) - mx);
        s1 += ex2f(fmaf(twoK, u.z, u.w) - mx);
        s2 += ex2f(fmaf(twoK, w.x, w.y) - mx);
        s3 += ex2f(fmaf(twoK, w.z, w.w) - mx);
    }
    float s = (s0 + s1) + (s2 + s3);
    return -(7.0f + mx + lg2f(s));
}

// One block per (b,s) problem: 20 Sinkhorn iterations + write transport plan.
__global__ void __launch_bounds__(128) sinkhorn_kernel(const float* __restrict__ X,
                                                       const float* __restrict__ Y) {
    __shared__ __align__(16) float2 sx[DD];  // {x_i, a_i}
    __shared__ __align__(16) float2 sy[DD];  // {y_j, b_j}

    const int p = blockIdx.x;
    const int t = threadIdx.x;

    const float x = X[(size_t)p * DD + t];
    const float y = Y[(size_t)p * DD + t];
    const float twoKx = TWOK * x;
    const float twoKy = TWOK * y;

    sx[t] = make_float2(x, -KCOEF * x * x);  // phi = 0 initially
    sy[t] = make_float2(y, -KCOEF * y * y);  // gamma = 0 initially
    __syncthreads();

    float b_new = 0.f;
    for (int it = 0; it < NITER; ++it) {
        // f-update: row i = t, reduce over columns j (reads sy, writes sx)
        float a_new = sweep_update(sy, twoKx);
        sx[t].y = a_new;
        __syncthreads();
        // g-update: column j = t, reduce over rows i (reads sx, writes sy)
        b_new = sweep_update(sx, twoKy);
        sy[t].y = b_new;
        __syncthreads();
    }

    // Transport plan: thread t = column j, loop rows i -> coalesced stores.
    // plan_ij = 2^(a_i + b_j + twoK * x_i * y_j)
    float* dst = g_scratch + (size_t)p * (DD * DD) + t;
    const float bj = b_new;
#pragma unroll 8
    for (int i = 0; i < DD; ++i) {
        float2 q = sx[i];
        dst[(size_t)i * DD] = ex2f(fmaf(twoKy, q.x, q.y) + bj);
    }
}

// Stage 1 reduction: 16 chunks of 128 plans each.
__global__ void __launch_bounds__(256) reduce_a_kernel() {
    const int idx = blockIdx.x * 256 + threadIdx.x;  // 0..16383
    const int c = blockIdx.y;                        // 0..15
    const float* src = g_scratch + (size_t)c * 128 * (DD * DD) + idx;
    float s = 0.f;
#pragma unroll 8
    for (int q = 0; q < 128; ++q) s += src[(size_t)q * (DD * DD)];
    g_partial[c * (DD * DD) + idx] = s;
}

// Stage 2 reduction + scale + delta -> ot matrix.
__global__ void __launch_bounds__(256) reduce_b_kernel(const float* __restrict__ delta) {
    const int idx = blockIdx.x * 256 + threadIdx.x;
    float s = 0.f;
#pragma unroll
    for (int c = 0; c < 16; ++c) s += g_partial[c * (DD * DD) + idx];
    g_ot[idx] = fmaf(s, OTSCALE, delta[idx]);
}

// out[p, :] = X[p, :] @ ot  (ot is 64KB, L1/L2 resident)
__global__ void __launch_bounds__(128) gemm_out_kernel(const float* __restrict__ X,
                                                       float* __restrict__ out) {
    __shared__ float xs[DD];
    const int p = blockIdx.x;
    const int t = threadIdx.x;
    xs[t] = X[(size_t)p * DD + t];
    __syncthreads();
    float a0 = 0.f, a1 = 0.f, a2 = 0.f, a3 = 0.f;
#pragma unroll 8
    for (int i = 0; i < DD; i += 4) {
        a0 = fmaf(xs[i + 0], g_ot[(i + 0) * DD + t], a0);
        a1 = fmaf(xs[i + 1], g_ot[(i + 1) * DD + t], a1);
        a2 = fmaf(xs[i + 2], g_ot[(i + 2) * DD + t], a2);
        a3 = fmaf(xs[i + 3], g_ot[(i + 3) * DD + t], a3);
    }
    out[(size_t)p * DD + t] = (a0 + a1) + (a2 + a3);
}

extern "C" void kernel_launch(void* const* d_in, const int* in_sizes, int n_in,
                              void* d_out, int out_size) {
    const float* X = (const float*)d_in[0];      // [8,256,128]
    const float* Y = (const float*)d_in[1];      // [8,256,128]
    const float* delta = (const float*)d_in[2];  // [128,128]
    float* out = (float*)d_out;                  // [8,256,128] float32

    sinkhorn_kernel<<<NPROB, 128>>>(X, Y);
    dim3 g2a(DD * DD / 256, 16);
    reduce_a_kernel<<<g2a, 256>>>();
    reduce_b_kernel<<<DD * DD / 256, 256>>>(delta);
    gemm_out_kernel<<<NPROB, 128>>>(X, out);
}

// round 2
// speedup vs baseline: 1.7095x; 1.7095x over previous
#include <cuda_runtime.h>
#include <cstdint>

// Problem constants
#define NPROB 2048      // B*S = 8*256
#define DD    128       // feature dim (m = n = 128)
#define NITER 20

// K = (SCALE/eps) * log2(e) = 3000 * log2(e)
#define KCOEF 4328.085098989891f
#define TWOK  8656.170197979782f
// ot scale: n * SCALE / NPROB = 128*300/2048
#define OTSCALE 18.75f

#define NCOPY   32
#define TH_SKIP 34.0f            // group-skip threshold below est. max (log2)
#define SMIN    2.44140625e-4f   // 2^-12 guard
#define SMAX    4096.0f          // 2^12 guard
#define PLAN_TH -35.0f           // plan entries below 2^-35 dropped
#define FIX_SCALE 1099511627776.0f // 2^40 fixed-point scale

__device__ unsigned long long g_accum[(size_t)NCOPY * DD * DD];
__device__ float g_ot[DD * DD];

__device__ __forceinline__ float ex2f(float x) {
    float r; asm("ex2.approx.ftz.f32 %0, %1;" : "=f"(r) : "f"(x)); return r;
}
__device__ __forceinline__ float lg2f(float x) {
    float r; asm("lg2.approx.f32 %0, %1;" : "=f"(r) : "f"(x)); return r;
}

// Full two-pass LSE sweep over 128 float2{coord,pot} entries (exact fallback).
// Returns new potential: -(7 + max_j v + log2(sum_j 2^(v-max))), v_j = twoKc*coord_j + pot_j
__device__ __forceinline__ float lse_full(const float2* __restrict__ arr, float twoKc) {
    const float4* a4 = reinterpret_cast<const float4*>(arr);
    float m0 = -1e30f, m1 = -1e30f, m2 = -1e30f, m3 = -1e30f;
#pragma unroll 8
    for (int q = 0; q < DD / 4; ++q) {
        float4 u = a4[2 * q];
        float4 w = a4[2 * q + 1];
        m0 = fmaxf(m0, fmaf(twoKc, u.x, u.y));
        m1 = fmaxf(m1, fmaf(twoKc, u.z, u.w));
        m2 = fmaxf(m2, fmaf(twoKc, w.x, w.y));
        m3 = fmaxf(m3, fmaf(twoKc, w.z, w.w));
    }
    float mx = fmaxf(fmaxf(m0, m1), fmaxf(m2, m3));
    float s0 = 0.f, s1 = 0.f, s2 = 0.f, s3 = 0.f;
#pragma unroll 8
    for (int q = 0; q < DD / 4; ++q) {
        float4 u = a4[2 * q];
        float4 w = a4[2 * q + 1];
        s0 += ex2f(fmaf(twoKc, u.x, u.y) - mx);
        s1 += ex2f(fmaf(twoKc, u.z, u.w) - mx);
        s2 += ex2f(fmaf(twoKc, w.x, w.y) - mx);
        s3 += ex2f(fmaf(twoKc, w.z, w.w) - mx);
    }
    float s = (s0 + s1) + (s2 + s3);
    return -(7.0f + mx + lg2f(s));
}

// Guarded sparse sum: sum of 2^(v - mx_est) over groups whose upper bound
// (twoKc * ext_coord + group pot max) exceeds mx_est - TH_SKIP for ANY lane.
// pmax[32]: group max of pots; eptr[32]: group extreme coord (hi if twoKc>=0).
__device__ __forceinline__ float guarded_sum(const float2* __restrict__ arr,
                                             const float* __restrict__ pmax,
                                             const float* __restrict__ eptr,
                                             float twoKc, float mx_est) {
    const float thr = mx_est - TH_SKIP;
    const float4* a4 = reinterpret_cast<const float4*>(arr);
    const float4* pm4 = reinterpret_cast<const float4*>(pmax);
    const float4* ex4 = reinterpret_cast<const float4*>(eptr);
    float sA = 0.f, sB = 0.f;
#pragma unroll
    for (int q = 0; q < 8; ++q) {
        float4 pm = pm4[q];
        float4 ex = ex4[q];
        int g = 4 * q;
        if (__any_sync(0xffffffffu, fmaf(twoKc, ex.x, pm.x) > thr)) {
            float4 u = a4[2 * g], w = a4[2 * g + 1];
            sA += ex2f(fmaf(twoKc, u.x, u.y) - mx_est);
            sB += ex2f(fmaf(twoKc, u.z, u.w) - mx_est);
            sA += ex2f(fmaf(twoKc, w.x, w.y) - mx_est);
            sB += ex2f(fmaf(twoKc, w.z, w.w) - mx_est);
        }
        if (__any_sync(0xffffffffu, fmaf(twoKc, ex.y, pm.y) > thr)) {
            float4 u = a4[2 * g + 2], w = a4[2 * g + 3];
            sA += ex2f(fmaf(twoKc, u.x, u.y) - mx_est);
            sB += ex2f(fmaf(twoKc, u.z, u.w) - mx_est);
            sA += ex2f(fmaf(twoKc, w.x, w.y) - mx_est);
            sB += ex2f(fmaf(twoKc, w.z, w.w) - mx_est);
        }
        if (__any_sync(0xffffffffu, fmaf(twoKc, ex.z, pm.z) > thr)) {
            float4 u = a4[2 * g + 4], w = a4[2 * g + 5];
            sA += ex2f(fmaf(twoKc, u.x, u.y) - mx_est);
            sB += ex2f(fmaf(twoKc, u.z, u.w) - mx_est);
            sA += ex2f(fmaf(twoKc, w.x, w.y) - mx_est);
            sB += ex2f(fmaf(twoKc, w.z, w.w) - mx_est);
        }
        if (__any_sync(0xffffffffu, fmaf(twoKc, ex.w, pm.w) > thr)) {
            float4 u = a4[2 * g + 6], w = a4[2 * g + 7];
            sA += ex2f(fmaf(twoKc, u.x, u.y) - mx_est);
            sB += ex2f(fmaf(twoKc, u.z, u.w) - mx_est);
            sA += ex2f(fmaf(twoKc, w.x, w.y) - mx_est);
            sB += ex2f(fmaf(twoKc, w.z, w.w) - mx_est);
        }
    }
    return sA + sB;
}

__global__ void __launch_bounds__(128) sinkhorn_kernel(const float* __restrict__ X,
                                                       const float* __restrict__ Y) {
    __shared__ __align__(16) float2 sx[DD];   // {sorted x, pot a}
    __shared__ __align__(16) float2 sy[DD];   // {sorted y, pot b}
    __shared__ int ox[DD], oy[DD];            // original indices
    __shared__ __align__(16) float kx[DD], ky[DD];          // sort keys
    __shared__ __align__(16) float apx[32], bpx[32];        // group pot maxes
    __shared__ __align__(16) float xlo[32], xhi[32], ylo[32], yhi[32];

    const int p = blockIdx.x;
    const int t = threadIdx.x;

    kx[t] = X[(size_t)p * DD + t]; ox[t] = t;
    ky[t] = Y[(size_t)p * DD + t]; oy[t] = t;
    __syncthreads();

    // Bitonic sort both (kx,ox) and (ky,oy) ascending; index tiebreak for total order.
    for (int k = 2; k <= DD; k <<= 1) {
        for (int j = k >> 1; j > 0; j >>= 1) {
            int prt = t ^ j;
            bool keep_small = ((t < prt) == ((t & k) == 0));
            float mkx = kx[t], pkx = kx[prt];
            int   mix = ox[t], pix = ox[prt];
            float mky = ky[t], pky = ky[prt];
            int   miy = oy[t], piy = oy[prt];
            __syncthreads();
            bool lessx = (mkx < pkx) || (mkx == pkx && mix < pix);
            bool takex = (lessx == keep_small);
            kx[t] = takex ? mkx : pkx;  ox[t] = takex ? mix : pix;
            bool lessy = (mky < pky) || (mky == pky && miy < piy);
            bool takey = (lessy == keep_small);
            ky[t] = takey ? mky : pky;  oy[t] = takey ? miy : piy;
            __syncthreads();
        }
    }

    const float x = kx[t];
    const float y = ky[t];
    const float twoKx = TWOK * x;
    const float twoKy = TWOK * y;
    float areg = -KCOEF * x * x;
    float breg = -KCOEF * y * y;
    sx[t] = make_float2(x, areg);
    sy[t] = make_float2(y, breg);
    if (t < 32) {
        xlo[t] = kx[4 * t]; xhi[t] = kx[4 * t + 3];
        ylo[t] = ky[4 * t]; yhi[t] = ky[4 * t + 3];
    }
    __syncthreads();

    const float* eyp = (twoKx >= 0.f) ? yhi : ylo;  // extreme y per group for f bound
    const float* exq = (twoKy >= 0.f) ? xhi : xlo;  // extreme x per group for g bound

    for (int it = 0; it < NITER; ++it) {
        // ---- f-update (rows; reduce over sy) ----
        float a_new = 0.f;
        bool full = (it == 0);
        if (!full) {
            float mx_est = -7.0f - areg;
            float s = guarded_sum(sy, bpx, eyp, twoKx, mx_est);
            bool bad = !(s >= SMIN && s <= SMAX);
            a_new = -(7.0f + mx_est + lg2f(s));
            full = __any_sync(0xffffffffu, bad);
        }
        if (full) a_new = lse_full(sy, twoKx);
        areg = a_new;
        float qa = a_new;
        qa = fmaxf(qa, __shfl_xor_sync(0xffffffffu, qa, 1));
        qa = fmaxf(qa, __shfl_xor_sync(0xffffffffu, qa, 2));
        sx[t].y = a_new;
        if ((t & 3) == 0) apx[t >> 2] = qa;
        __syncthreads();

        // ---- g-update (cols; reduce over sx) ----
        float b_new = 0.f;
        full = (it == 0);
        if (!full) {
            float mx_est = -7.0f - breg;
            float s = guarded_sum(sx, apx, exq, twoKy, mx_est);
            bool bad = !(s >= SMIN && s <= SMAX);
            b_new = -(7.0f + mx_est + lg2f(s));
            full = __any_sync(0xffffffffu, bad);
        }
        if (full) b_new = lse_full(sx, twoKy);
        breg = b_new;
        float qb = b_new;
        qb = fmaxf(qb, __shfl_xor_sync(0xffffffffu, qb, 1));
        qb = fmaxf(qb, __shfl_xor_sync(0xffffffffu, qb, 2));
        sy[t].y = b_new;
        if ((t & 3) == 0) bpx[t >> 2] = qb;
        __syncthreads();
    }

    // ---- Plan accumulation: thread t = sorted row t; fixed-point atomic adds ----
    // plan_ij = 2^(a_i + b_j + twoKx_i * y_j); skip groups bounded below 2^PLAN_TH.
    {
        const int oi = ox[t];
        unsigned long long* rowp =
            g_accum + (size_t)(p & (NCOPY - 1)) * (DD * DD) + (size_t)oi * DD;
        const float thr = PLAN_TH - areg;   // fire iff v_j > thr
        const float4* a4 = reinterpret_cast<const float4*>(sy);
        const float4* pm4 = reinterpret_cast<const float4*>(bpx);
        const float4* ex4 = reinterpret_cast<const float4*>(eyp);
#pragma unroll
        for (int q = 0; q < 8; ++q) {
            float4 pm = pm4[q];
            float4 ex = ex4[q];
#pragma unroll
            for (int h = 0; h < 4; ++h) {
                float bnd = (h == 0) ? fmaf(twoKx, ex.x, pm.x)
                          : (h == 1) ? fmaf(twoKx, ex.y, pm.y)
                          : (h == 2) ? fmaf(twoKx, ex.z, pm.z)
                                     : fmaf(twoKx, ex.w, pm.w);
                if (__any_sync(0xffffffffu, bnd > thr)) {
                    int g = 4 * q + h;
                    float4 u = a4[2 * g], w = a4[2 * g + 1];
                    float E0 = fmaf(twoKx, u.x, u.y) + areg;
                    float E1 = fmaf(twoKx, u.z, u.w) + areg;
                    float E2 = fmaf(twoKx, w.x, w.y) + areg;
                    float E3 = fmaf(twoKx, w.z, w.w) + areg;
                    if (E0 > -40.f)
                        atomicAdd(rowp + oy[4 * g + 0],
                                  (unsigned long long)(ex2f(E0) * FIX_SCALE));
                    if (E1 > -40.f)
                        atomicAdd(rowp + oy[4 * g + 1],
                                  (unsigned long long)(ex2f(E1) * FIX_SCALE));
                    if (E2 > -40.f)
                        atomicAdd(rowp + oy[4 * g + 2],
                                  (unsigned long long)(ex2f(E2) * FIX_SCALE));
                    if (E3 > -40.f)
                        atomicAdd(rowp + oy[4 * g + 3],
                                  (unsigned long long)(ex2f(E3) * FIX_SCALE));
                }
            }
        }
    }
}

__global__ void __launch_bounds__(256) zero_accum_kernel() {
    const int idx = blockIdx.x * 256 + threadIdx.x;
    g_accum[idx] = 0ull;
}

// Sum 32 fixed-point copies (exact integer sum -> deterministic), scale, add delta.
__global__ void __launch_bounds__(256) reduce_b_kernel(const float* __restrict__ delta) {
    const int idx = blockIdx.x * 256 + threadIdx.x;
    unsigned long long tot = 0ull;
#pragma unroll
    for (int c = 0; c < NCOPY; ++c) tot += g_accum[(size_t)c * (DD * DD) + idx];
    g_ot[idx] = (float)((double)tot * ((double)OTSCALE / (double)FIX_SCALE)) + delta[idx];
}

// out[p, :] = X[p, :] @ ot  (ot is 64KB, L2 resident)
__global__ void __launch_bounds__(128) gemm_out_kernel(const float* __restrict__ X,
                                                       float* __restrict__ out) {
    __shared__ float xs[DD];
    const int p = blockIdx.x;
    const int t = threadIdx.x;
    xs[t] = X[(size_t)p * DD + t];
    __syncthreads();
    float a0 = 0.f, a1 = 0.f, a2 = 0.f, a3 = 0.f;
#pragma unroll 8
    for (int i = 0; i < DD; i += 4) {
        a0 = fmaf(xs[i + 0], g_ot[(i + 0) * DD + t], a0);
        a1 = fmaf(xs[i + 1], g_ot[(i + 1) * DD + t], a1);
        a2 = fmaf(xs[i + 2], g_ot[(i + 2) * DD + t], a2);
        a3 = fmaf(xs[i + 3], g_ot[(i + 3) * DD + t], a3);
    }
    out[(size_t)p * DD + t] = (a0 + a1) + (a2 + a3);
}

extern "C" void kernel_launch(void* const* d_in, const int* in_sizes, int n_in,
                              void* d_out, int out_size) {
    const float* X = (const float*)d_in[0];      // [8,256,128]
    const float* Y = (const float*)d_in[1];      // [8,256,128]
    const float* delta = (const float*)d_in[2];  // [128,128]
    float* out = (float*)d_out;                  // [8,256,128] float32

    zero_accum_kernel<<<(NCOPY * DD * DD) / 256, 256>>>();
    sinkhorn_kernel<<<NPROB, 128>>>(X, Y);
    reduce_b_kernel<<<(DD * DD) / 256, 256>>>(delta);
    gemm_out_kernel<<<NPROB, 128>>>(X, out);
}